// round 2
// baseline (speedup 1.0000x reference)
#include <cuda_runtime.h>
#include <cstdint>
#include <cstddef>

// ---------------- problem constants ----------------
#define MAXPTS 300000
#define CC 128            // channels
#define NSC 4             // number of scales
#define COORDN 512u
#define NSLOTS (1u<<19)   // hash slots (>= ~300k distinct keys, load <= 0.58)
#define SLOT_MASK (NSLOTS-1u)
#define EMPTY_KEY 0xFFFFFFFFu
#define EPSV 1e-5f
#define SLOPEV 0.01f

#define BM 64             // GEMM rows per block
#define PADM (BM+4)       // padded row stride for OsT (multiple of 4)

// ---------------- device scratch (static; zero-initialized at module load) ----
__device__ unsigned g_keys[NSLOTS];
__device__ int      g_counts[NSLOTS];
__device__ float    g_sums[(size_t)NSLOTS * CC];   // 256 MB; invariant: zero between scales
__device__ unsigned g_slotflag[MAXPTS];            // slot | (singleton << 31)
__device__ int      g_list[MAXPTS];                // compacted non-singleton point ids
__device__ int      g_nnz;
__device__ float    g_chanSum[CC];
__device__ float    g_chanSq[CC];
__device__ float    g_A[CC];                       // BN scale
__device__ float    g_Bc[CC];                      // BN shift
__device__ float    g_sv[CC];                      // final value for singleton rows

__device__ __forceinline__ unsigned hash32(unsigned x) {
    x ^= x >> 16; x *= 0x7feb352dU;
    x ^= x >> 15; x *= 0x846ca68bU;
    x ^= x >> 16;
    return x;
}

// ---------------- kernels ----------------

__global__ void k_clear() {
    unsigned i = blockIdx.x * blockDim.x + threadIdx.x;
    if (i < NSLOTS) { g_keys[i] = EMPTY_KEY; g_counts[i] = 0; }
    if (i == 0) g_nnz = 0;
}

__global__ void k_build(const int* __restrict__ idx, int shift, int M) {
    int p = blockIdx.x * blockDim.x + threadIdx.x;
    if (p >= M) return;
    unsigned b  = (unsigned)idx[p * 4 + 0];
    unsigned cx = (unsigned)idx[p * 4 + 1] >> shift;
    unsigned cy = (unsigned)idx[p * 4 + 2] >> shift;
    unsigned cz = (unsigned)idx[p * 4 + 3] >> shift;
    unsigned key = ((b * COORDN + cx) * COORDN + cy) * COORDN + cz;
    unsigned slot = hash32(key) & SLOT_MASK;
    while (true) {
        unsigned prev = atomicCAS(&g_keys[slot], EMPTY_KEY, key);
        if (prev == EMPTY_KEY || prev == key) break;
        slot = (slot + 1u) & SLOT_MASK;
    }
    g_slotflag[p] = slot;
    atomicAdd(&g_counts[slot], 1);
}

__global__ void k_flag(int M) {
    int p = blockIdx.x * blockDim.x + threadIdx.x;
    if (p >= M) return;
    unsigned slot = g_slotflag[p];
    int c = g_counts[slot];
    if (c > 1) {
        int pos = atomicAdd(&g_nnz, 1);
        g_list[pos] = p;
    } else {
        g_slotflag[p] = slot | 0x80000000u;   // singleton: Os row is exactly 0
    }
}

// one warp-lane group of 32 threads per listed point; each thread a float4
__global__ void k_accum(const float* __restrict__ feats) {
    int g = blockIdx.x * blockDim.x + threadIdx.x;
    int li = g >> 5;
    if (li >= g_nnz) return;
    int lane = g & 31;
    int p = g_list[li];
    unsigned slot = g_slotflag[p] & 0x7FFFFFFFu;
    float4 v = *(const float4*)(feats + (size_t)p * CC + lane * 4);
    float* dst = g_sums + (size_t)slot * CC + lane * 4;
    atomicAdd(dst + 0, v.x);
    atomicAdd(dst + 1, v.y);
    atomicAdd(dst + 2, v.z);
    atomicAdd(dst + 3, v.w);
}

// re-zero only the slots that were accumulated (keeps invariant for next scale / replay)
__global__ void k_zero_slots() {
    int g = blockIdx.x * blockDim.x + threadIdx.x;
    int li = g >> 5;
    if (li >= g_nnz) return;
    int lane = g & 31;
    int p = g_list[li];
    unsigned slot = g_slotflag[p] & 0x7FFFFFFFu;
    *(float4*)(g_sums + (size_t)slot * CC + lane * 4) = make_float4(0.f, 0.f, 0.f, 0.f);
}

// fused: Os row construction + 64x128 GEMM tile + b add + per-channel sum/sumsq
__global__ __launch_bounds__(256, 2)
void k_gemm(const float* __restrict__ feats, const float* __restrict__ W,
            const float* __restrict__ bvec, float* __restrict__ out, int scale_i) {
    int base = blockIdx.x * BM;
    int nnz = g_nnz;
    if (base >= nnz) return;

    extern __shared__ float sm[];
    float* Wsm = sm;                 // [128][128]
    float* OsT = sm + CC * CC;       // [128][PADM]  (k-major, transposed)
    __shared__ float bsum[CC];
    __shared__ float bsq[CC];

    int tid = threadIdx.x;
    if (tid < CC) { bsum[tid] = 0.f; bsq[tid] = 0.f; }

    // load W[scale] into smem
    const float* Wp = W + (size_t)scale_i * CC * CC;
    for (int i = tid; i < CC * CC / 4; i += 256)
        ((float4*)Wsm)[i] = ((const float4*)Wp)[i];

    // build OsT: 4 threads per row, 32 k each
    {
        int rr = tid >> 2;      // 0..63
        int kg = tid & 3;       // 0..3
        int li = base + rr;
        bool valid = li < nnz;
        int p = valid ? g_list[li] : 0;
        unsigned slot = g_slotflag[p] & 0x7FFFFFFFu;
        float invc = valid ? 1.0f / (float)g_counts[slot] : 0.f;
        const float* fp = feats + (size_t)p * CC;
        const float* sp = g_sums + (size_t)slot * CC;
        #pragma unroll
        for (int it = 0; it < 8; it++) {
            int k = kg * 32 + it * 4;
            float4 f = valid ? *(const float4*)(fp + k) : make_float4(0.f, 0.f, 0.f, 0.f);
            float4 s = valid ? *(const float4*)(sp + k) : make_float4(0.f, 0.f, 0.f, 0.f);
            OsT[(k + 0) * PADM + rr] = (f.x - s.x * invc) * f.x;
            OsT[(k + 1) * PADM + rr] = (f.y - s.y * invc) * f.y;
            OsT[(k + 2) * PADM + rr] = (f.z - s.z * invc) * f.z;
            OsT[(k + 3) * PADM + rr] = (f.w - s.w * invc) * f.w;
        }
    }
    __syncthreads();

    // 8x4 register micro-tile per thread: rows cy*8.., cols cx*4..
    int cx = tid & 31;
    int cy = tid >> 5;
    float acc[8][4];
    #pragma unroll
    for (int r = 0; r < 8; r++)
        #pragma unroll
        for (int c = 0; c < 4; c++) acc[r][c] = 0.f;

    #pragma unroll 4
    for (int k = 0; k < CC; k++) {
        float4 bv = *(const float4*)(Wsm + k * CC + (cx << 2));
        float4 a0 = *(const float4*)(OsT + k * PADM + (cy << 3));
        float4 a1 = *(const float4*)(OsT + k * PADM + (cy << 3) + 4);
        float a[8] = {a0.x, a0.y, a0.z, a0.w, a1.x, a1.y, a1.z, a1.w};
        float bb[4] = {bv.x, bv.y, bv.z, bv.w};
        #pragma unroll
        for (int r = 0; r < 8; r++)
            #pragma unroll
            for (int c = 0; c < 4; c++)
                acc[r][c] += a[r] * bb[c];
    }

    // epilogue: add b, store raw h to output slice, accumulate BN stats
    float4 bb4 = *(const float4*)(bvec + scale_i * CC + (cx << 2));
    float psum[4] = {0.f, 0.f, 0.f, 0.f};
    float psq[4]  = {0.f, 0.f, 0.f, 0.f};
    #pragma unroll
    for (int r = 0; r < 8; r++) {
        int li = base + (cy << 3) + r;
        if (li < nnz) {
            int p = g_list[li];
            float4 h;
            h.x = acc[r][0] + bb4.x;
            h.y = acc[r][1] + bb4.y;
            h.z = acc[r][2] + bb4.z;
            h.w = acc[r][3] + bb4.w;
            *(float4*)(out + ((size_t)p * NSC + scale_i) * CC + (cx << 2)) = h;
            psum[0] += h.x; psum[1] += h.y; psum[2] += h.z; psum[3] += h.w;
            psq[0] += h.x * h.x; psq[1] += h.y * h.y;
            psq[2] += h.z * h.z; psq[3] += h.w * h.w;
        }
    }
    #pragma unroll
    for (int c = 0; c < 4; c++) {
        atomicAdd(&bsum[(cx << 2) + c], psum[c]);
        atomicAdd(&bsq[(cx << 2) + c],  psq[c]);
    }
    __syncthreads();
    if (tid < CC) {
        atomicAdd(&g_chanSum[tid], bsum[tid]);
        atomicAdd(&g_chanSq[tid],  bsq[tid]);
    }
}

__global__ void k_finalize(const float* __restrict__ bvec, const float* __restrict__ gamma,
                           const float* __restrict__ beta, int scale_i, int M) {
    int c = threadIdx.x;      // 128 threads
    int nnz = g_nnz;
    float bc = bvec[scale_i * CC + c];
    float rem = (float)(M - nnz);
    float sum = g_chanSum[c] + rem * bc;
    float sq  = g_chanSq[c]  + rem * bc * bc;
    float mu  = sum / (float)M;
    float var = sq / (float)M - mu * mu;
    float A = rsqrtf(var + EPSV) * gamma[scale_i * CC + c];
    float B = beta[scale_i * CC + c] - mu * A;
    g_A[c]  = A;
    g_Bc[c] = B;
    float t = bc * A + B;
    g_sv[c] = t > 0.f ? t : SLOPEV * t;
    g_chanSum[c] = 0.f;       // reset for next scale / next replay
    g_chanSq[c]  = 0.f;
}

__global__ void k_norm(float* __restrict__ out, int scale_i, int M) {
    int g = blockIdx.x * blockDim.x + threadIdx.x;
    int p = g >> 5;
    if (p >= M) return;
    int c4 = (g & 31) << 2;
    unsigned sf = g_slotflag[p];
    float* op = out + ((size_t)p * NSC + scale_i) * CC + c4;
    float4 v;
    if (sf & 0x80000000u) {
        v = *(const float4*)(g_sv + c4);   // precomputed BN(leaky(b))
    } else {
        float4 h = *(const float4*)op;
        v.x = h.x * g_A[c4 + 0] + g_Bc[c4 + 0];
        v.y = h.y * g_A[c4 + 1] + g_Bc[c4 + 1];
        v.z = h.z * g_A[c4 + 2] + g_Bc[c4 + 2];
        v.w = h.w * g_A[c4 + 3] + g_Bc[c4 + 3];
        v.x = v.x > 0.f ? v.x : SLOPEV * v.x;
        v.y = v.y > 0.f ? v.y : SLOPEV * v.y;
        v.z = v.z > 0.f ? v.z : SLOPEV * v.z;
        v.w = v.w > 0.f ? v.w : SLOPEV * v.w;
    }
    *(float4*)op = v;
}

// ---------------- launcher ----------------
extern "C" void kernel_launch(void* const* d_in, const int* in_sizes, int n_in,
                              void* d_out, int out_size) {
    const float* feats = (const float*)d_in[0];
    const int*   idx   = (const int*)d_in[1];
    const float* W     = (const float*)d_in[2];
    const float* bvec  = (const float*)d_in[3];
    const float* gamma = (const float*)d_in[4];
    const float* beta  = (const float*)d_in[5];
    float* out = (float*)d_out;

    int M = in_sizes[0] / CC;   // 300000

    size_t smem = (size_t)(CC * CC + CC * PADM) * sizeof(float);   // ~98 KB
    cudaFuncSetAttribute(k_gemm, cudaFuncAttributeMaxDynamicSharedMemorySize, (int)smem);

    int grid_slots = (NSLOTS + 255) / 256;
    int grid_pts   = (M + 255) / 256;
    int grid_lane  = (M * 32 + 255) / 256;
    int grid_gemm  = (M + BM - 1) / BM;

    const int shifts[NSC] = {1, 2, 3, 4};   // SCALES = 2,4,8,16

    for (int i = 0; i < NSC; i++) {
        k_clear<<<grid_slots, 256>>>();
        k_build<<<grid_pts, 256>>>(idx, shifts[i], M);
        k_flag<<<grid_pts, 256>>>(M);
        k_accum<<<grid_lane, 256>>>(feats);
        k_gemm<<<grid_gemm, 256, smem>>>(feats, W, bvec, out, i);
        k_zero_slots<<<grid_lane, 256>>>();
        k_finalize<<<1, CC>>>(bvec, gamma, beta, i, M);
        k_norm<<<grid_lane, 256>>>(out, i, M);
    }
}

// round 7
// speedup vs baseline: 1.0429x; 1.0429x over previous
#include <cuda_runtime.h>
#include <cuda_bf16.h>
#include <cstdint>
#include <cstddef>

// ---------------- problem constants ----------------
#define MAXPTS 300000
#define CC 128            // channels
#define NSC 4             // number of scales
#define COORDN 512u
#define NSLOTS (1u<<19)
#define SLOT_MASK (NSLOTS-1u)
#define EMPTY_KEY 0xFFFFFFFFu
#define EPSV 1e-5f
#define SLOPEV 0.01f

#define TM 128            // rows per CTA tile
#define SP 136            // smem row stride in bf16 elements (272B -> conflict-free)

// ---------------- device scratch ----------------
__device__ unsigned g_keys[NSLOTS];
__device__ int      g_counts[NSLOTS];
__device__ float    g_sums[(size_t)NSLOTS * CC];   // invariant: zero between scales
__device__ unsigned g_slotflag[MAXPTS];
__device__ int      g_list[MAXPTS];
__device__ int      g_nnz;
__device__ float    g_chanSum[CC];
__device__ float    g_chanSq[CC];
__device__ float    g_A[CC];
__device__ float    g_Bc[CC];
__device__ float    g_sv[CC];
__device__ __nv_bfloat16 g_WtHi[NSC * CC * CC];    // Wt[n][k] = bf16_hi(W[k][n])
__device__ __nv_bfloat16 g_WtLo[NSC * CC * CC];

__device__ __forceinline__ unsigned hash32(unsigned x) {
    x ^= x >> 16; x *= 0x7feb352dU;
    x ^= x >> 15; x *= 0x846ca68bU;
    x ^= x >> 16;
    return x;
}

__device__ __forceinline__ void mma_bf16(float& d0, float& d1, float& d2, float& d3,
                                         uint32_t a0, uint32_t a1, uint32_t a2, uint32_t a3,
                                         uint32_t b0, uint32_t b1) {
    asm volatile(
        "mma.sync.aligned.m16n8k16.row.col.f32.bf16.bf16.f32 "
        "{%0,%1,%2,%3}, {%4,%5,%6,%7}, {%8,%9}, {%0,%1,%2,%3};\n"
        : "+f"(d0), "+f"(d1), "+f"(d2), "+f"(d3)
        : "r"(a0), "r"(a1), "r"(a2), "r"(a3), "r"(b0), "r"(b1));
}

// ---------------- kernels ----------------

__global__ void k_clear() {
    unsigned i = blockIdx.x * blockDim.x + threadIdx.x;
    if (i < NSLOTS) { g_keys[i] = EMPTY_KEY; g_counts[i] = 0; }
    if (i == 0) g_nnz = 0;
}

__global__ void k_prep(const float* __restrict__ W) {
    int i = blockIdx.x * blockDim.x + threadIdx.x;   // s*16384 + n*128 + k
    if (i >= NSC * CC * CC) return;
    int s = i >> 14, rem = i & 16383, n = rem >> 7, k = rem & 127;
    float v = W[(size_t)s * CC * CC + k * CC + n];
    __nv_bfloat16 hi = __float2bfloat16_rn(v);
    __nv_bfloat16 lo = __float2bfloat16_rn(v - __bfloat162float(hi));
    g_WtHi[i] = hi;
    g_WtLo[i] = lo;
}

__global__ void k_build(const int* __restrict__ idx, int shift, int M) {
    int p = blockIdx.x * blockDim.x + threadIdx.x;
    if (p >= M) return;
    unsigned b  = (unsigned)idx[p * 4 + 0];
    unsigned cx = (unsigned)idx[p * 4 + 1] >> shift;
    unsigned cy = (unsigned)idx[p * 4 + 2] >> shift;
    unsigned cz = (unsigned)idx[p * 4 + 3] >> shift;
    unsigned key = ((b * COORDN + cx) * COORDN + cy) * COORDN + cz;
    unsigned slot = hash32(key) & SLOT_MASK;
    while (true) {
        unsigned prev = atomicCAS(&g_keys[slot], EMPTY_KEY, key);
        if (prev == EMPTY_KEY || prev == key) break;
        slot = (slot + 1u) & SLOT_MASK;
    }
    g_slotflag[p] = slot;
    atomicAdd(&g_counts[slot], 1);
}

__global__ void k_flag(int M) {
    int p = blockIdx.x * blockDim.x + threadIdx.x;
    if (p >= M) return;
    unsigned slot = g_slotflag[p];
    int c = g_counts[slot];
    if (c > 1) {
        int pos = atomicAdd(&g_nnz, 1);
        g_list[pos] = p;
    } else {
        g_slotflag[p] = slot | 0x80000000u;
    }
}

__global__ void k_accum(const float* __restrict__ feats) {
    int g = blockIdx.x * blockDim.x + threadIdx.x;
    int li = g >> 5;
    if (li >= g_nnz) return;
    int lane = g & 31;
    int p = g_list[li];
    unsigned slot = g_slotflag[p] & 0x7FFFFFFFu;
    float4 v = *(const float4*)(feats + (size_t)p * CC + lane * 4);
    float* dst = g_sums + (size_t)slot * CC + lane * 4;
    atomicAdd(dst + 0, v.x);
    atomicAdd(dst + 1, v.y);
    atomicAdd(dst + 2, v.z);
    atomicAdd(dst + 3, v.w);
}

__global__ void k_zero_slots() {
    int g = blockIdx.x * blockDim.x + threadIdx.x;
    int li = g >> 5;
    if (li >= g_nnz) return;
    int lane = g & 31;
    int p = g_list[li];
    unsigned slot = g_slotflag[p] & 0x7FFFFFFFu;
    *(float4*)(g_sums + (size_t)slot * CC + lane * 4) = make_float4(0.f, 0.f, 0.f, 0.f);
}

// ---- HMMA bf16 split GEMM: h = Os @ W + b on the non-singleton rows ----
// Os = Ahi + Alo, Wt = Bhi + Blo ; acc += AhiBhi + AhiBlo + AloBhi (fp32)
__global__ __launch_bounds__(256, 1)
void k_gemm_mma(const float* __restrict__ feats, const float* __restrict__ bvec,
                float* __restrict__ out, int scale_i) {
    int nnz = g_nnz;
    int base = blockIdx.x * TM;
    if (base >= nnz) return;

    extern __shared__ __nv_bfloat16 sm[];
    __nv_bfloat16* AHI = sm;                 // [128][SP]
    __nv_bfloat16* ALO = sm + 128 * SP;
    __nv_bfloat16* BHI = sm + 2 * 128 * SP;
    __nv_bfloat16* BLO = sm + 3 * 128 * SP;
    __shared__ float bsum[CC], bsq[CC], bsh[CC];

    int tid = threadIdx.x;
    int wid = tid >> 5;
    int lane = tid & 31;

    if (tid < CC) {
        bsum[tid] = 0.f; bsq[tid] = 0.f;
        bsh[tid] = bvec[scale_i * CC + tid];
    }

    // --- stage B: 2 threads per n-row, 64 k each ---
    {
        int n = tid >> 1, kh = (tid & 1) << 6;
        const uint32_t* whi = (const uint32_t*)(g_WtHi + (size_t)scale_i * CC * CC + n * CC + kh);
        const uint32_t* wlo = (const uint32_t*)(g_WtLo + (size_t)scale_i * CC * CC + n * CC + kh);
        uint32_t* dh = (uint32_t*)(BHI + n * SP + kh);
        uint32_t* dl = (uint32_t*)(BLO + n * SP + kh);
        #pragma unroll 8
        for (int kk = 0; kk < 32; kk++) { dh[kk] = whi[kk]; dl[kk] = wlo[kk]; }
    }

    // --- stage A (Os hi/lo): 2 threads per m-row, 64 k each ---
    {
        int rr = tid >> 1, kh = (tid & 1) << 6;
        int li = base + rr;
        bool valid = li < nnz;
        int p = valid ? g_list[li] : 0;
        unsigned slot = g_slotflag[p] & 0x7FFFFFFFu;
        float invc = valid ? 1.0f / (float)g_counts[slot] : 0.f;
        const float* fp = feats + (size_t)p * CC + kh;
        const float* sp = g_sums + (size_t)slot * CC + kh;
        uint32_t* dh = (uint32_t*)(AHI + rr * SP + kh);
        uint32_t* dl = (uint32_t*)(ALO + rr * SP + kh);
        #pragma unroll 4
        for (int k = 0; k < 64; k += 4) {
            float4 f = valid ? *(const float4*)(fp + k) : make_float4(0.f, 0.f, 0.f, 0.f);
            float4 s = valid ? *(const float4*)(sp + k) : make_float4(0.f, 0.f, 0.f, 0.f);
            float o0 = (f.x - s.x * invc) * f.x;
            float o1 = (f.y - s.y * invc) * f.y;
            float o2 = (f.z - s.z * invc) * f.z;
            float o3 = (f.w - s.w * invc) * f.w;
            __nv_bfloat162 h0 = __floats2bfloat162_rn(o0, o1);
            __nv_bfloat162 h1 = __floats2bfloat162_rn(o2, o3);
            __nv_bfloat162 l0 = __floats2bfloat162_rn(o0 - __bfloat162float(h0.x),
                                                      o1 - __bfloat162float(h0.y));
            __nv_bfloat162 l1 = __floats2bfloat162_rn(o2 - __bfloat162float(h1.x),
                                                      o3 - __bfloat162float(h1.y));
            dh[(k >> 1)]     = *(uint32_t*)&h0;
            dh[(k >> 1) + 1] = *(uint32_t*)&h1;
            dl[(k >> 1)]     = *(uint32_t*)&l0;
            dl[(k >> 1) + 1] = *(uint32_t*)&l1;
        }
    }
    __syncthreads();

    // --- mma mainloop: each warp owns 16 rows x 128 cols ---
    // acc[ntile]: d0,d1 = row lane/4, cols (lane%4)*2+{0,1}+ntile*8; d2,d3 = row+8
    float acc[16][4];
    #pragma unroll
    for (int n = 0; n < 16; n++)
        #pragma unroll
        for (int j = 0; j < 4; j++) acc[n][j] = 0.f;

    int arow = wid * 16 + (lane >> 2);      // A row for frag regs a0/a2 (a1/a3 = +8)
    int kq = (lane & 3) << 1;               // k pair base within k-tile

    #pragma unroll
    for (int kt = 0; kt < 8; kt++) {
        int k0 = kt * 16 + kq;
        uint32_t ah0 = *(uint32_t*)(AHI + arow * SP + k0);
        uint32_t ah1 = *(uint32_t*)(AHI + (arow + 8) * SP + k0);
        uint32_t ah2 = *(uint32_t*)(AHI + arow * SP + k0 + 8);
        uint32_t ah3 = *(uint32_t*)(AHI + (arow + 8) * SP + k0 + 8);
        uint32_t al0 = *(uint32_t*)(ALO + arow * SP + k0);
        uint32_t al1 = *(uint32_t*)(ALO + (arow + 8) * SP + k0);
        uint32_t al2 = *(uint32_t*)(ALO + arow * SP + k0 + 8);
        uint32_t al3 = *(uint32_t*)(ALO + (arow + 8) * SP + k0 + 8);
        #pragma unroll
        for (int n = 0; n < 16; n++) {
            int brow = n * 8 + (lane >> 2);
            uint32_t bh0 = *(uint32_t*)(BHI + brow * SP + k0);
            uint32_t bh1 = *(uint32_t*)(BHI + brow * SP + k0 + 8);
            uint32_t bl0 = *(uint32_t*)(BLO + brow * SP + k0);
            uint32_t bl1 = *(uint32_t*)(BLO + brow * SP + k0 + 8);
            mma_bf16(acc[n][0], acc[n][1], acc[n][2], acc[n][3],
                     ah0, ah1, ah2, ah3, bh0, bh1);
            mma_bf16(acc[n][0], acc[n][1], acc[n][2], acc[n][3],
                     ah0, ah1, ah2, ah3, bl0, bl1);
            mma_bf16(acc[n][0], acc[n][1], acc[n][2], acc[n][3],
                     al0, al1, al2, al3, bh0, bh1);
        }
    }

    // --- epilogue: h = acc + b; store raw h; per-channel sum/sumsq ---
    int r0 = base + wid * 16 + (lane >> 2);
    int r1 = r0 + 8;
    bool v0 = r0 < nnz, v1 = r1 < nnz;
    int p0 = v0 ? g_list[r0] : 0;
    int p1 = v1 ? g_list[r1] : 0;
    float* o0 = out + ((size_t)p0 * NSC + scale_i) * CC;
    float* o1 = out + ((size_t)p1 * NSC + scale_i) * CC;

    #pragma unroll
    for (int n = 0; n < 16; n++) {
        int c0 = n * 8 + ((lane & 3) << 1);
        float bx = bsh[c0], by = bsh[c0 + 1];
        float h0x = acc[n][0] + bx, h0y = acc[n][1] + by;
        float h1x = acc[n][2] + bx, h1y = acc[n][3] + by;
        if (v0) *(float2*)(o0 + c0) = make_float2(h0x, h0y);
        if (v1) *(float2*)(o1 + c0) = make_float2(h1x, h1y);
        float sx = (v0 ? h0x : 0.f) + (v1 ? h1x : 0.f);
        float sy = (v0 ? h0y : 0.f) + (v1 ? h1y : 0.f);
        float qx = (v0 ? h0x * h0x : 0.f) + (v1 ? h1x * h1x : 0.f);
        float qy = (v0 ? h0y * h0y : 0.f) + (v1 ? h1y * h1y : 0.f);
        #pragma unroll
        for (int o = 4; o < 32; o <<= 1) {
            sx += __shfl_xor_sync(0xFFFFFFFFu, sx, o);
            sy += __shfl_xor_sync(0xFFFFFFFFu, sy, o);
            qx += __shfl_xor_sync(0xFFFFFFFFu, qx, o);
            qy += __shfl_xor_sync(0xFFFFFFFFu, qy, o);
        }
        if (lane < 4) {
            atomicAdd(&bsum[c0],     sx);
            atomicAdd(&bsum[c0 + 1], sy);
            atomicAdd(&bsq[c0],      qx);
            atomicAdd(&bsq[c0 + 1],  qy);
        }
    }
    __syncthreads();
    if (tid < CC) {
        atomicAdd(&g_chanSum[tid], bsum[tid]);
        atomicAdd(&g_chanSq[tid],  bsq[tid]);
    }
}

__global__ void k_finalize(const float* __restrict__ bvec, const float* __restrict__ gamma,
                           const float* __restrict__ beta, int scale_i, int M) {
    int c = threadIdx.x;
    int nnz = g_nnz;
    float bc = bvec[scale_i * CC + c];
    float rem = (float)(M - nnz);
    float sum = g_chanSum[c] + rem * bc;
    float sq  = g_chanSq[c]  + rem * bc * bc;
    float mu  = sum / (float)M;
    float var = sq / (float)M - mu * mu;
    float A = rsqrtf(var + EPSV) * gamma[scale_i * CC + c];
    float B = beta[scale_i * CC + c] - mu * A;
    g_A[c]  = A;
    g_Bc[c] = B;
    float t = bc * A + B;
    g_sv[c] = t > 0.f ? t : SLOPEV * t;
    g_chanSum[c] = 0.f;
    g_chanSq[c]  = 0.f;
}

__global__ void k_norm(float* __restrict__ out, int scale_i, int M) {
    int g = blockIdx.x * blockDim.x + threadIdx.x;
    int p = g >> 5;
    if (p >= M) return;
    int c4 = (g & 31) << 2;
    unsigned sf = g_slotflag[p];
    float* op = out + ((size_t)p * NSC + scale_i) * CC + c4;
    float4 v;
    if (sf & 0x80000000u) {
        v = *(const float4*)(g_sv + c4);
    } else {
        float4 h = *(const float4*)op;
        v.x = h.x * g_A[c4 + 0] + g_Bc[c4 + 0];
        v.y = h.y * g_A[c4 + 1] + g_Bc[c4 + 1];
        v.z = h.z * g_A[c4 + 2] + g_Bc[c4 + 2];
        v.w = h.w * g_A[c4 + 3] + g_Bc[c4 + 3];
        v.x = v.x > 0.f ? v.x : SLOPEV * v.x;
        v.y = v.y > 0.f ? v.y : SLOPEV * v.y;
        v.z = v.z > 0.f ? v.z : SLOPEV * v.z;
        v.w = v.w > 0.f ? v.w : SLOPEV * v.w;
    }
    *(float4*)op = v;
}

// ---------------- launcher ----------------
extern "C" void kernel_launch(void* const* d_in, const int* in_sizes, int n_in,
                              void* d_out, int out_size) {
    const float* feats = (const float*)d_in[0];
    const int*   idx   = (const int*)d_in[1];
    const float* W     = (const float*)d_in[2];
    const float* bvec  = (const float*)d_in[3];
    const float* gamma = (const float*)d_in[4];
    const float* beta  = (const float*)d_in[5];
    float* out = (float*)d_out;

    int M = in_sizes[0] / CC;   // 300000

    size_t smem_mma = (size_t)4 * 128 * SP * sizeof(__nv_bfloat16);   // 139264 B
    cudaFuncSetAttribute(k_gemm_mma, cudaFuncAttributeMaxDynamicSharedMemorySize,
                         (int)smem_mma);

    int grid_slots = (NSLOTS + 255) / 256;
    int grid_pts   = (M + 255) / 256;
    int grid_lane  = (M * 32 + 255) / 256;
    int grid_gemm  = (M + TM - 1) / TM;
    int grid_prep  = (NSC * CC * CC + 255) / 256;

    const int shifts[NSC] = {1, 2, 3, 4};   // SCALES = 2,4,8,16

    k_prep<<<grid_prep, 256>>>(W);

    for (int i = 0; i < NSC; i++) {
        k_clear<<<grid_slots, 256>>>();
        k_build<<<grid_pts, 256>>>(idx, shifts[i], M);
        k_flag<<<grid_pts, 256>>>(M);
        k_accum<<<grid_lane, 256>>>(feats);
        k_gemm_mma<<<grid_gemm, 256, smem_mma>>>(feats, bvec, out, i);
        k_zero_slots<<<grid_lane, 256>>>();
        k_finalize<<<1, CC>>>(bvec, gamma, beta, i, M);
        k_norm<<<grid_lane, 256>>>(out, i, M);
    }
}